// round 3
// baseline (speedup 1.0000x reference)
#include <cuda_runtime.h>
#include <math.h>
#include <stdint.h>

#define N_NODES  100000
#define N_EDGES  3200000
#define HID      128
#define N_GRAPHS 512
#define N_CLASSES 10
#define BN_EPS   1e-5f

// ---------------- scratch (device globals; no allocations) ----------------
__device__ float g_h[N_NODES * HID];     // layer output h
__device__ float g_z[N_NODES * HID];     // aggregated input z
__device__ int   g_deg[N_NODES];
__device__ int   g_off[N_NODES + 1];
__device__ int   g_cur[N_NODES];
__device__ int   g_csr[N_EDGES];         // src ids grouped by dst
__device__ float g_pool[N_GRAPHS * HID];
__device__ float g_cnt[N_GRAPHS];

// ---------------- CSR build ----------------
__global__ void k_zero() {
    int i = blockIdx.x * blockDim.x + threadIdx.x;
    if (i < N_NODES) g_deg[i] = 0;
    if (i < N_GRAPHS * HID) g_pool[i] = 0.0f;
    if (i < N_GRAPHS) g_cnt[i] = 0.0f;
}

__global__ void k_hist(const int* __restrict__ dst) {
    int e = blockIdx.x * blockDim.x + threadIdx.x;
    if (e < N_EDGES) atomicAdd(&g_deg[dst[e]], 1);
}

// single-block exclusive scan: serial per-thread chunks + 2-level shuffle scan
__global__ void k_scan() {
    __shared__ int warpsum[32];
    const int tid = threadIdx.x;                 // 1024 threads
    const int C = (N_NODES + 1023) / 1024;
    const int beg = tid * C;
    const int end = min(beg + C, N_NODES);

    int sum = 0;
    for (int i = beg; i < end; i++) sum += g_deg[i];

    int lane = tid & 31, wid = tid >> 5;
    int v = sum;
#pragma unroll
    for (int d = 1; d < 32; d <<= 1) {
        int t = __shfl_up_sync(0xffffffffu, v, d);
        if (lane >= d) v += t;
    }
    if (lane == 31) warpsum[wid] = v;
    __syncthreads();
    if (wid == 0) {
        int w = warpsum[lane];
#pragma unroll
        for (int d = 1; d < 32; d <<= 1) {
            int t = __shfl_up_sync(0xffffffffu, w, d);
            if (lane >= d) w += t;
        }
        warpsum[lane] = w;
    }
    __syncthreads();
    int excl = v - sum + (wid > 0 ? warpsum[wid - 1] : 0);

    int run = excl;
    for (int i = beg; i < end; i++) {
        int d = g_deg[i];
        g_off[i] = run;
        g_cur[i] = run;
        run += d;
    }
    if (tid == 1023) g_off[N_NODES] = run;
}

__global__ void k_scatter(const int* __restrict__ src, const int* __restrict__ dst) {
    int e = blockIdx.x * blockDim.x + threadIdx.x;
    if (e < N_EDGES) {
        int pos = atomicAdd(&g_cur[dst[e]], 1);
        g_csr[pos] = src[e];
    }
}

// ---------------- aggregation: z = (1+eps)*h + sum_{src in N(dst)} h[src] ----------------
__global__ void k_agg(const float* __restrict__ x, int layer, const float* __restrict__ epsp) {
    int node = (blockIdx.x * blockDim.x + threadIdx.x) >> 5;
    int lane = threadIdx.x & 31;
    if (node >= N_NODES) return;
    const float* hin = (layer == 0) ? x : (const float*)g_h;
    const float4* hv = (const float4*)hin;
    int beg = g_off[node], end = g_off[node + 1];
    float4 acc = make_float4(0.f, 0.f, 0.f, 0.f);
    for (int base = beg; base < end; base += 32) {
        int n = min(32, end - base);
        int s = (lane < n) ? g_csr[base + lane] : 0;
#pragma unroll 4
        for (int j = 0; j < n; j++) {
            int sj = __shfl_sync(0xffffffffu, s, j);
            float4 v = hv[sj * 32 + lane];
            acc.x += v.x; acc.y += v.y; acc.z += v.z; acc.w += v.w;
        }
    }
    float e = 1.0f + epsp[layer];
    float4 self = hv[node * 32 + lane];
    acc.x += e * self.x; acc.y += e * self.y;
    acc.z += e * self.z; acc.w += e * self.w;
    ((float4*)g_z)[node * 32 + lane] = acc;
}

// ---------------- fused MLP via tf32 tensor cores (2-term split = fp32-accurate) --------
#define SA   132                      // sZ row stride (floats)
#define SWP  132                      // sW row stride (float2 units)
#define SMEM_MLP ((HID * SA) * 4 + (HID * SWP) * 8)

__device__ __forceinline__ uint32_t f2tf32(float f) {
    uint32_t r;
    asm("cvt.rna.tf32.f32 %0, %1;" : "=r"(r) : "f"(f));
    return r;
}

__device__ __forceinline__ void mma_tf32(float d[4], uint32_t a0, uint32_t a1,
                                         uint32_t a2, uint32_t a3,
                                         uint32_t b0, uint32_t b1) {
    asm("mma.sync.aligned.m16n8k8.row.col.f32.tf32.tf32.f32 "
        "{%0,%1,%2,%3},{%4,%5,%6,%7},{%8,%9},{%0,%1,%2,%3};"
        : "+f"(d[0]), "+f"(d[1]), "+f"(d[2]), "+f"(d[3])
        : "r"(a0), "r"(a1), "r"(a2), "r"(a3), "r"(b0), "r"(b1));
}

// load W (row-major [128][128]) into smem as (hi, lo) tf32 pairs
__device__ __forceinline__ void load_W_split(const float* __restrict__ W, float2* sW, int tid) {
    for (int i = tid; i < HID * HID; i += 256) {
        int k = i >> 7, n = i & 127;
        float v = W[i];
        uint32_t hi = f2tf32(v);
        float lo_f = v - __uint_as_float(hi);
        uint32_t lo = f2tf32(lo_f);
        sW[k * SWP + n] = make_float2(__uint_as_float(hi), __uint_as_float(lo));
    }
}

// D[128x128] += A(sZ fp32)[128x128] @ B(sW split)[128x128]; warp handles 16 rows
__device__ __forceinline__ void gemm_tf32(const float* __restrict__ sZ,
                                          const float2* __restrict__ sW,
                                          int m0, int g, int tig, float d[16][4]) {
    const int rowA = m0 + g;
#pragma unroll 4
    for (int kt = 0; kt < 16; kt++) {
        int colA = kt * 8 + tig;
        float va0 = sZ[rowA * SA + colA];
        float va1 = sZ[(rowA + 8) * SA + colA];
        float va2 = sZ[rowA * SA + colA + 4];
        float va3 = sZ[(rowA + 8) * SA + colA + 4];
        uint32_t a0h = f2tf32(va0), a1h = f2tf32(va1), a2h = f2tf32(va2), a3h = f2tf32(va3);
        uint32_t a0l = f2tf32(va0 - __uint_as_float(a0h));
        uint32_t a1l = f2tf32(va1 - __uint_as_float(a1h));
        uint32_t a2l = f2tf32(va2 - __uint_as_float(a2h));
        uint32_t a3l = f2tf32(va3 - __uint_as_float(a3h));
        int rowB0 = kt * 8 + tig;
#pragma unroll
        for (int nt = 0; nt < 16; nt++) {
            int colB = nt * 8 + g;
            float2 p0 = sW[rowB0 * SWP + colB];
            float2 p1 = sW[(rowB0 + 4) * SWP + colB];
            uint32_t b0h = __float_as_uint(p0.x), b1h = __float_as_uint(p1.x);
            uint32_t b0l = __float_as_uint(p0.y), b1l = __float_as_uint(p1.y);
            mma_tf32(d[nt], a0h, a1h, a2h, a3h, b0h, b1h);
            mma_tf32(d[nt], a0h, a1h, a2h, a3h, b0l, b1l);
            mma_tf32(d[nt], a0l, a1l, a2l, a3l, b0h, b1h);
        }
    }
}

__global__ void __launch_bounds__(256, 1)
k_mlp(const float* __restrict__ W1, const float* __restrict__ b1,
      const float* __restrict__ W2, const float* __restrict__ b2,
      const float* __restrict__ gamma, const float* __restrict__ beta,
      const float* __restrict__ mu, const float* __restrict__ var) {
    extern __shared__ float smem[];
    float*  sZ = smem;                          // [128][SA] fp32
    float2* sW = (float2*)(smem + HID * SA);    // [128][SWP] (hi,lo)
    const int tid = threadIdx.x;                // 256 threads = 8 warps
    const int warp = tid >> 5, lane = tid & 31;
    const int g = lane >> 2, tig = lane & 3;
    const int m0 = warp * 16;
    const int rowBase = blockIdx.x * 128;

    // load z tile (zero-pad OOB rows)
    for (int i = tid; i < 128 * 32; i += 256) {
        int r = i >> 5, c4 = i & 31;
        int gr = rowBase + r;
        float4 v = (gr < N_NODES) ? ((const float4*)g_z)[gr * 32 + c4]
                                  : make_float4(0.f, 0.f, 0.f, 0.f);
        float* p = &sZ[r * SA + c4 * 4];
        p[0] = v.x; p[1] = v.y; p[2] = v.z; p[3] = v.w;
    }
    load_W_split(W1, sW, tid);
    __syncthreads();

    float d[16][4];
#pragma unroll
    for (int nt = 0; nt < 16; nt++)
#pragma unroll
        for (int j = 0; j < 4; j++) d[nt][j] = 0.f;
    gemm_tf32(sZ, sW, m0, g, tig, d);
    __syncthreads();   // all smem reads done

    // mid = relu(d + b1) -> back into sZ ; reload sW with W2 split
#pragma unroll
    for (int nt = 0; nt < 16; nt++) {
        int col = nt * 8 + 2 * tig;
        float bc0 = b1[col], bc1 = b1[col + 1];
        float v0 = fmaxf(d[nt][0] + bc0, 0.f);
        float v1 = fmaxf(d[nt][1] + bc1, 0.f);
        float v2 = fmaxf(d[nt][2] + bc0, 0.f);
        float v3 = fmaxf(d[nt][3] + bc1, 0.f);
        *(float2*)&sZ[(m0 + g) * SA + col]     = make_float2(v0, v1);
        *(float2*)&sZ[(m0 + g + 8) * SA + col] = make_float2(v2, v3);
    }
    load_W_split(W2, sW, tid);
    __syncthreads();

#pragma unroll
    for (int nt = 0; nt < 16; nt++)
#pragma unroll
        for (int j = 0; j < 4; j++) d[nt][j] = 0.f;
    gemm_tf32(sZ, sW, m0, g, tig, d);

    // epilogue: bias2 + relu + batchnorm, store to g_h
    int gr0 = rowBase + m0 + g;
    int gr1 = gr0 + 8;
#pragma unroll
    for (int nt = 0; nt < 16; nt++) {
        int col = nt * 8 + 2 * tig;
        float bc0 = b2[col], bc1 = b2[col + 1];
        float sc0 = gamma[col] * rsqrtf(var[col] + BN_EPS);
        float sc1 = gamma[col + 1] * rsqrtf(var[col + 1] + BN_EPS);
        float mu0 = mu[col], mu1 = mu[col + 1];
        float be0 = beta[col], be1 = beta[col + 1];
        if (gr0 < N_NODES) {
            float v0 = (fmaxf(d[nt][0] + bc0, 0.f) - mu0) * sc0 + be0;
            float v1 = (fmaxf(d[nt][1] + bc1, 0.f) - mu1) * sc1 + be1;
            *(float2*)&g_h[gr0 * HID + col] = make_float2(v0, v1);
        }
        if (gr1 < N_NODES) {
            float v2 = (fmaxf(d[nt][2] + bc0, 0.f) - mu0) * sc0 + be0;
            float v3 = (fmaxf(d[nt][3] + bc1, 0.f) - mu1) * sc1 + be1;
            *(float2*)&g_h[gr1 * HID + col] = make_float2(v2, v3);
        }
    }
}

// ---------------- pooling ----------------
__global__ void k_pool(const int* __restrict__ batch) {
    int idx = blockIdx.x * blockDim.x + threadIdx.x;
    int node = idx >> 5, lane = idx & 31;
    if (node >= N_NODES) return;
    int b = batch[node];
    float4 v = ((const float4*)g_h)[node * 32 + lane];
    float* p = &g_pool[b * HID + lane * 4];
    atomicAdd(p + 0, v.x);
    atomicAdd(p + 1, v.y);
    atomicAdd(p + 2, v.z);
    atomicAdd(p + 3, v.w);
    if (lane == 0) atomicAdd(&g_cnt[b], 1.0f);
}

// ---------------- head: mean, lin1+relu, lin2, log_softmax ----------------
__global__ void k_head(const float* __restrict__ l1w, const float* __restrict__ l1b,
                       const float* __restrict__ l2w, const float* __restrict__ l2b,
                       float* __restrict__ out) {
    __shared__ float p[HID], q[HID], r[N_CLASSES];
    int g = blockIdx.x, tid = threadIdx.x;   // 128 threads
    float cnt = fmaxf(g_cnt[g], 1.0f);
    p[tid] = g_pool[g * HID + tid] / cnt;
    __syncthreads();
    float acc = l1b[tid];
    for (int k = 0; k < HID; k++) acc += p[k] * l1w[k * HID + tid];
    q[tid] = fmaxf(acc, 0.f);
    __syncthreads();
    if (tid < N_CLASSES) {
        float a2 = l2b[tid];
        for (int k = 0; k < HID; k++) a2 += q[k] * l2w[k * N_CLASSES + tid];
        r[tid] = a2;
    }
    __syncthreads();
    if (tid < N_CLASSES) {
        float m = -INFINITY;
        for (int j = 0; j < N_CLASSES; j++) m = fmaxf(m, r[j]);
        float s = 0.f;
        for (int j = 0; j < N_CLASSES; j++) s += expf(r[j] - m);
        out[g * N_CLASSES + tid] = r[tid] - m - logf(s);
    }
}

// ---------------- launch ----------------
extern "C" void kernel_launch(void* const* d_in, const int* in_sizes, int n_in,
                              void* d_out, int out_size) {
    const float* x        = (const float*)d_in[0];
    const int*   eidx     = (const int*)d_in[1];
    const int*   batch    = (const int*)d_in[2];
    const float* W1       = (const float*)d_in[3];
    const float* b1       = (const float*)d_in[4];
    const float* W2       = (const float*)d_in[5];
    const float* b2       = (const float*)d_in[6];
    const float* gamma    = (const float*)d_in[7];
    const float* beta     = (const float*)d_in[8];
    const float* bn_mean  = (const float*)d_in[9];
    const float* bn_var   = (const float*)d_in[10];
    const float* eps      = (const float*)d_in[11];
    const float* lin1_w   = (const float*)d_in[12];
    const float* lin1_b   = (const float*)d_in[13];
    const float* lin2_w   = (const float*)d_in[14];
    const float* lin2_b   = (const float*)d_in[15];
    float* out = (float*)d_out;

    const int* src = eidx;
    const int* dst = eidx + N_EDGES;

    cudaFuncSetAttribute(k_mlp, cudaFuncAttributeMaxDynamicSharedMemorySize, SMEM_MLP);

    k_zero<<<(N_NODES + 255) / 256, 256>>>();
    k_hist<<<(N_EDGES + 255) / 256, 256>>>(dst);
    k_scan<<<1, 1024>>>();
    k_scatter<<<(N_EDGES + 255) / 256, 256>>>(src, dst);

    for (int l = 0; l < 3; l++) {
        k_agg<<<(N_NODES * 32 + 255) / 256, 256>>>(x, l, eps);
        k_mlp<<<(N_NODES + 127) / 128, 256, SMEM_MLP>>>(
            W1 + l * HID * HID, b1 + l * HID,
            W2 + l * HID * HID, b2 + l * HID,
            gamma + l * HID, beta + l * HID,
            bn_mean + l * HID, bn_var + l * HID);
    }

    k_pool<<<(N_NODES * 32 + 255) / 256, 256>>>(batch);
    k_head<<<N_GRAPHS, HID>>>(lin1_w, lin1_b, lin2_w, lin2_b, out);
}

// round 6
// speedup vs baseline: 1.6637x; 1.6637x over previous
#include <cuda_runtime.h>
#include <cuda_bf16.h>
#include <math.h>
#include <stdint.h>

#define N_NODES  100000
#define N_EDGES  3200000
#define HID      128
#define N_GRAPHS 512
#define N_CLASSES 10
#define BN_EPS   1e-5f

// ---------------- scratch (device globals; no allocations) ----------------
__device__ float g_h[N_NODES * HID];
__device__ float g_z[N_NODES * HID];
__device__ int   g_deg[N_NODES];
__device__ int   g_off[N_NODES + 1];
__device__ int   g_cur[N_NODES];
__device__ int   g_csr[N_EDGES];
__device__ float g_pool[N_GRAPHS * HID];
__device__ float g_cnt[N_GRAPHS];

// ---------------- CSR build ----------------
__global__ void k_zero() {
    int i = blockIdx.x * blockDim.x + threadIdx.x;
    if (i < N_NODES) g_deg[i] = 0;
    if (i < N_GRAPHS * HID) g_pool[i] = 0.0f;
    if (i < N_GRAPHS) g_cnt[i] = 0.0f;
}

__global__ void k_hist(const int* __restrict__ dst) {
    int e = blockIdx.x * blockDim.x + threadIdx.x;
    if (e < N_EDGES) atomicAdd(&g_deg[dst[e]], 1);
}

__global__ void k_scan() {
    __shared__ int warpsum[32];
    const int tid = threadIdx.x;
    const int C = (N_NODES + 1023) / 1024;
    const int beg = tid * C;
    const int end = min(beg + C, N_NODES);
    int sum = 0;
    for (int i = beg; i < end; i++) sum += g_deg[i];
    int lane = tid & 31, wid = tid >> 5;
    int v = sum;
#pragma unroll
    for (int d = 1; d < 32; d <<= 1) {
        int t = __shfl_up_sync(0xffffffffu, v, d);
        if (lane >= d) v += t;
    }
    if (lane == 31) warpsum[wid] = v;
    __syncthreads();
    if (wid == 0) {
        int w = warpsum[lane];
#pragma unroll
        for (int d = 1; d < 32; d <<= 1) {
            int t = __shfl_up_sync(0xffffffffu, w, d);
            if (lane >= d) w += t;
        }
        warpsum[lane] = w;
    }
    __syncthreads();
    int excl = v - sum + (wid > 0 ? warpsum[wid - 1] : 0);
    int run = excl;
    for (int i = beg; i < end; i++) {
        int d = g_deg[i];
        g_off[i] = run;
        g_cur[i] = run;
        run += d;
    }
    if (tid == 1023) g_off[N_NODES] = run;
}

__global__ void k_scatter(const int* __restrict__ src, const int* __restrict__ dst) {
    int e = blockIdx.x * blockDim.x + threadIdx.x;
    if (e < N_EDGES) {
        int pos = atomicAdd(&g_cur[dst[e]], 1);
        g_csr[pos] = src[e];
    }
}

// ---------------- aggregation ----------------
__global__ void k_agg(const float* __restrict__ x, int layer, const float* __restrict__ epsp) {
    int node = (blockIdx.x * blockDim.x + threadIdx.x) >> 5;
    int lane = threadIdx.x & 31;
    if (node >= N_NODES) return;
    const float* hin = (layer == 0) ? x : (const float*)g_h;
    const float4* hv = (const float4*)hin;
    int beg = g_off[node], end = g_off[node + 1];
    float4 acc = make_float4(0.f, 0.f, 0.f, 0.f);
    for (int base = beg; base < end; base += 32) {
        int n = min(32, end - base);
        int s = (lane < n) ? g_csr[base + lane] : 0;
#pragma unroll 4
        for (int j = 0; j < n; j++) {
            int sj = __shfl_sync(0xffffffffu, s, j);
            float4 v = hv[sj * 32 + lane];
            acc.x += v.x; acc.y += v.y; acc.z += v.z; acc.w += v.w;
        }
    }
    float e = 1.0f + epsp[layer];
    float4 self = hv[node * 32 + lane];
    acc.x += e * self.x; acc.y += e * self.y;
    acc.z += e * self.z; acc.w += e * self.w;
    ((float4*)g_z)[node * 32 + lane] = acc;
}

// ---------------- MLP via bf16 mma.sync (hi/lo split, 3-pass) ----------------
#define STR   136                      // bf16 row stride (272B, 16B-aligned rows)
#define T_BYTES (HID * STR * 2)        // 34816 per tile
#define OFF_AHI 0
#define OFF_ALO (T_BYTES)
#define OFF_BHI (2 * T_BYTES)
#define OFF_BLO (3 * T_BYTES)
#define SMEM_MMA (4 * T_BYTES)

__device__ __forceinline__ uint32_t smem_u32(const void* p) {
    uint32_t a;
    asm("{ .reg .u64 t; cvta.to.shared.u64 t, %1; cvt.u32.u64 %0, t; }" : "=r"(a) : "l"(p));
    return a;
}

// pack (v0 lower, v1 upper) into bf16x2 hi + residual-lo
__device__ __forceinline__ void pack2(float v0, float v1, uint32_t& hi, uint32_t& lo) {
    uint32_t h;
    asm("cvt.rn.bf16x2.f32 %0, %1, %2;" : "=r"(h) : "f"(v1), "f"(v0));
    float h0 = __uint_as_float(h << 16);
    float h1 = __uint_as_float(h & 0xffff0000u);
    asm("cvt.rn.bf16x2.f32 %0, %1, %2;" : "=r"(lo) : "f"(v1 - h1), "f"(v0 - h0));
    hi = h;
}

#define LDSM_X4(r0, r1, r2, r3, a)                                                 \
    asm volatile("ldmatrix.sync.aligned.m8n8.x4.shared.b16 {%0,%1,%2,%3}, [%4];"   \
        : "=r"(r0), "=r"(r1), "=r"(r2), "=r"(r3) : "r"(a))
#define LDSM_X4T(r0, r1, r2, r3, a)                                                \
    asm volatile("ldmatrix.sync.aligned.m8n8.x4.trans.shared.b16 {%0,%1,%2,%3}, [%4];" \
        : "=r"(r0), "=r"(r1), "=r"(r2), "=r"(r3) : "r"(a))
#define MMA16816(d, a, b0, b1)                                                     \
    asm volatile("mma.sync.aligned.m16n8k16.row.col.f32.bf16.bf16.f32 "            \
        "{%0,%1,%2,%3},{%4,%5,%6,%7},{%8,%9},{%0,%1,%2,%3};"                       \
        : "+f"((d)[0]), "+f"((d)[1]), "+f"((d)[2]), "+f"((d)[3])                   \
        : "r"((a)[0]), "r"((a)[1]), "r"((a)[2]), "r"((a)[3]), "r"(b0), "r"(b1))

// fill a [128 rows][128 cols] bf16 hi/lo tile pair from fp32 row-major source
__device__ __forceinline__ void fill_tile(const float* __restrict__ srcRow0,
                                          int rowStrideValid, char* smem,
                                          int offHi, int offLo, int tid) {
    for (int i = tid; i < 128 * 32; i += 256) {
        int r = i >> 5, c4 = (i & 31) * 4;
        float4 v = (r < rowStrideValid) ? *(const float4*)(srcRow0 + r * HID + c4)
                                        : make_float4(0.f, 0.f, 0.f, 0.f);
        uint32_t h01, l01, h23, l23;
        pack2(v.x, v.y, h01, l01);
        pack2(v.z, v.w, h23, l23);
        uint32_t boff = (uint32_t)(r * STR + c4) * 2;
        *(uint2*)(smem + offHi + boff) = make_uint2(h01, h23);
        *(uint2*)(smem + offLo + boff) = make_uint2(l01, l23);
    }
}

// D[128x128] += A[128x128] @ B[128x128] (B stored K-major, ldmatrix.trans)
__device__ __forceinline__ void gemm_mma(uint32_t sb, int warpM, int lane,
                                         float acc[16][4]) {
    const int lr = lane & 7, lj = lane >> 3;
    // A: matrix j -> m_off=(j&1)*8, k_off=(j>>1)*8
    const uint32_t aOff = (uint32_t)((warpM + ((lj & 1) << 3) + lr) * STR
                                     + ((lj >> 1) << 3)) * 2;
    // B (k-major rows): matrix j -> k_off=(j>>1)*8, n_off=(j&1)*8
    const uint32_t bRowPart = (uint32_t)((((lj >> 1) << 3) + lr) * STR
                                         + ((lj & 1) << 3)) * 2;
#pragma unroll 2
    for (int kt = 0; kt < 8; kt++) {
        uint32_t ah[4], al[4];
        uint32_t aAddr = sb + OFF_AHI + aOff + kt * 32;       // kt*16 cols * 2B
        LDSM_X4(ah[0], ah[1], ah[2], ah[3], aAddr);
        LDSM_X4(al[0], al[1], al[2], al[3], aAddr + (OFF_ALO - OFF_AHI));
        uint32_t bBase = sb + OFF_BHI + bRowPart + (uint32_t)(kt * 16 * STR) * 2;
#pragma unroll
        for (int q = 0; q < 8; q++) {
            uint32_t bh[4], bl[4];
            uint32_t bAddr = bBase + q * 32;                   // q*16 cols * 2B
            LDSM_X4T(bh[0], bh[1], bh[2], bh[3], bAddr);
            LDSM_X4T(bl[0], bl[1], bl[2], bl[3], bAddr + (OFF_BLO - OFF_BHI));
            MMA16816(acc[2 * q],     ah, bh[0], bh[2]);
            MMA16816(acc[2 * q],     ah, bl[0], bl[2]);
            MMA16816(acc[2 * q],     al, bh[0], bh[2]);
            MMA16816(acc[2 * q + 1], ah, bh[1], bh[3]);
            MMA16816(acc[2 * q + 1], ah, bl[1], bl[3]);
            MMA16816(acc[2 * q + 1], al, bh[1], bh[3]);
        }
    }
}

__global__ void __launch_bounds__(256, 1)
k_mlp_mma(const float* __restrict__ W1, const float* __restrict__ b1,
          const float* __restrict__ W2, const float* __restrict__ b2,
          const float* __restrict__ gamma, const float* __restrict__ beta,
          const float* __restrict__ mu, const float* __restrict__ var) {
    extern __shared__ __align__(16) char smem[];
    const uint32_t sb = smem_u32(smem);
    const int tid = threadIdx.x;
    const int warp = tid >> 5, lane = tid & 31;
    const int warpM = warp * 16;
    const int rowBase = blockIdx.x * 128;
    const int validRows = min(128, N_NODES - rowBase);

    // fill A from g_z (zero-pad OOB), B from W1 (K-major, no transpose)
    fill_tile(g_z + (size_t)rowBase * HID, validRows, smem, OFF_AHI, OFF_ALO, tid);
    fill_tile(W1, 128, smem, OFF_BHI, OFF_BLO, tid);
    __syncthreads();

    float acc[16][4];
#pragma unroll
    for (int p = 0; p < 16; p++)
#pragma unroll
        for (int j = 0; j < 4; j++) acc[p][j] = 0.f;
    gemm_mma(sb, warpM, lane, acc);

    // mid epilogue: relu(acc + b1) -> rewrite OWN A rows (no sync needed: own rows)
    {
        const int r = lane >> 2, cB = (lane & 3) * 2;
        const int row0 = warpM + r, row1 = row0 + 8;
#pragma unroll
        for (int p = 0; p < 16; p++) {
            int c = p * 8 + cB;
            float2 bb = __ldg((const float2*)&b1[c]);
            float v00 = fmaxf(acc[p][0] + bb.x, 0.f);
            float v01 = fmaxf(acc[p][1] + bb.y, 0.f);
            float v10 = fmaxf(acc[p][2] + bb.x, 0.f);
            float v11 = fmaxf(acc[p][3] + bb.y, 0.f);
            uint32_t h, l;
            pack2(v00, v01, h, l);
            *(uint32_t*)(smem + OFF_AHI + (row0 * STR + c) * 2) = h;
            *(uint32_t*)(smem + OFF_ALO + (row0 * STR + c) * 2) = l;
            pack2(v10, v11, h, l);
            *(uint32_t*)(smem + OFF_AHI + (row1 * STR + c) * 2) = h;
            *(uint32_t*)(smem + OFF_ALO + (row1 * STR + c) * 2) = l;
        }
    }
    __syncthreads();                       // everyone done reading B(W1)
    fill_tile(W2, 128, smem, OFF_BHI, OFF_BLO, tid);
    __syncthreads();

#pragma unroll
    for (int p = 0; p < 16; p++)
#pragma unroll
        for (int j = 0; j < 4; j++) acc[p][j] = 0.f;
    gemm_mma(sb, warpM, lane, acc);

    // final epilogue: bias2 + relu + BN -> g_h
    {
        const int r = lane >> 2, cB = (lane & 3) * 2;
        const int gr0 = rowBase + warpM + r, gr1 = gr0 + 8;
#pragma unroll
        for (int p = 0; p < 16; p++) {
            int c = p * 8 + cB;
            float2 bb = __ldg((const float2*)&b2[c]);
            float2 gm = __ldg((const float2*)&gamma[c]);
            float2 vr = __ldg((const float2*)&var[c]);
            float2 mm = __ldg((const float2*)&mu[c]);
            float2 be = __ldg((const float2*)&beta[c]);
            float sc0 = gm.x * rsqrtf(vr.x + BN_EPS);
            float sc1 = gm.y * rsqrtf(vr.y + BN_EPS);
            float sh0 = be.x - mm.x * sc0;
            float sh1 = be.y - mm.y * sc1;
            if (gr0 < N_NODES) {
                float o0 = fmaxf(acc[p][0] + bb.x, 0.f) * sc0 + sh0;
                float o1 = fmaxf(acc[p][1] + bb.y, 0.f) * sc1 + sh1;
                *(float2*)&g_h[(size_t)gr0 * HID + c] = make_float2(o0, o1);
            }
            if (gr1 < N_NODES) {
                float o0 = fmaxf(acc[p][2] + bb.x, 0.f) * sc0 + sh0;
                float o1 = fmaxf(acc[p][3] + bb.y, 0.f) * sc1 + sh1;
                *(float2*)&g_h[(size_t)gr1 * HID + c] = make_float2(o0, o1);
            }
        }
    }
}

// ---------------- pooling ----------------
__global__ void k_pool(const int* __restrict__ batch) {
    int idx = blockIdx.x * blockDim.x + threadIdx.x;
    int node = idx >> 5, lane = idx & 31;
    if (node >= N_NODES) return;
    int b = batch[node];
    float4 v = ((const float4*)g_h)[node * 32 + lane];
    float* p = &g_pool[b * HID + lane * 4];
    atomicAdd(p + 0, v.x);
    atomicAdd(p + 1, v.y);
    atomicAdd(p + 2, v.z);
    atomicAdd(p + 3, v.w);
    if (lane == 0) atomicAdd(&g_cnt[b], 1.0f);
}

// ---------------- head ----------------
__global__ void k_head(const float* __restrict__ l1w, const float* __restrict__ l1b,
                       const float* __restrict__ l2w, const float* __restrict__ l2b,
                       float* __restrict__ out) {
    __shared__ float p[HID], q[HID], r[N_CLASSES];
    int g = blockIdx.x, tid = threadIdx.x;
    float cnt = fmaxf(g_cnt[g], 1.0f);
    p[tid] = g_pool[g * HID + tid] / cnt;
    __syncthreads();
    float acc = l1b[tid];
    for (int k = 0; k < HID; k++) acc += p[k] * l1w[k * HID + tid];
    q[tid] = fmaxf(acc, 0.f);
    __syncthreads();
    if (tid < N_CLASSES) {
        float a2 = l2b[tid];
        for (int k = 0; k < HID; k++) a2 += q[k] * l2w[k * N_CLASSES + tid];
        r[tid] = a2;
    }
    __syncthreads();
    if (tid < N_CLASSES) {
        float m = -INFINITY;
        for (int j = 0; j < N_CLASSES; j++) m = fmaxf(m, r[j]);
        float s = 0.f;
        for (int j = 0; j < N_CLASSES; j++) s += expf(r[j] - m);
        out[g * N_CLASSES + tid] = r[tid] - m - logf(s);
    }
}

// ---------------- launch ----------------
extern "C" void kernel_launch(void* const* d_in, const int* in_sizes, int n_in,
                              void* d_out, int out_size) {
    const float* x        = (const float*)d_in[0];
    const int*   eidx     = (const int*)d_in[1];
    const int*   batch    = (const int*)d_in[2];
    const float* W1       = (const float*)d_in[3];
    const float* b1       = (const float*)d_in[4];
    const float* W2       = (const float*)d_in[5];
    const float* b2       = (const float*)d_in[6];
    const float* gamma    = (const float*)d_in[7];
    const float* beta     = (const float*)d_in[8];
    const float* bn_mean  = (const float*)d_in[9];
    const float* bn_var   = (const float*)d_in[10];
    const float* eps      = (const float*)d_in[11];
    const float* lin1_w   = (const float*)d_in[12];
    const float* lin1_b   = (const float*)d_in[13];
    const float* lin2_w   = (const float*)d_in[14];
    const float* lin2_b   = (const float*)d_in[15];
    float* out = (float*)d_out;

    const int* src = eidx;
    const int* dst = eidx + N_EDGES;

    cudaFuncSetAttribute(k_mlp_mma, cudaFuncAttributeMaxDynamicSharedMemorySize, SMEM_MMA);

    k_zero<<<(N_NODES + 255) / 256, 256>>>();
    k_hist<<<(N_EDGES + 255) / 256, 256>>>(dst);
    k_scan<<<1, 1024>>>();
    k_scatter<<<(N_EDGES + 255) / 256, 256>>>(src, dst);

    for (int l = 0; l < 3; l++) {
        k_agg<<<(N_NODES * 32 + 255) / 256, 256>>>(x, l, eps);
        k_mlp_mma<<<(N_NODES + 127) / 128, 256, SMEM_MMA>>>(
            W1 + l * HID * HID, b1 + l * HID,
            W2 + l * HID * HID, b2 + l * HID,
            gamma + l * HID, beta + l * HID,
            bn_mean + l * HID, bn_var + l * HID);
    }

    k_pool<<<(N_NODES * 32 + 255) / 256, 256>>>(batch);
    k_head<<<N_GRAPHS, HID>>>(lin1_w, lin1_b, lin2_w, lin2_b, out);
}